// round 9
// baseline (speedup 1.0000x reference)
#include <cuda_runtime.h>
#include <cuda_fp16.h>
#include <stdint.h>

// ---------------- problem constants ----------------
#define NE    8
#define DIN   2048
#define DOUT  2048
#define NTOK  8192
#define NPAIR (NTOK * 2)

// ---------------- GEMM tiling ----------------
#define BM     128
#define BN     128
#define BK     64
#define ASTR   72                  // padded smem row stride (halves); conflict-free LDSM
#define KSTEPS (DIN / BK)          // 32
#define NTILE  (DOUT / BN)         // 16
#define MAXT   136
#define MAXROWS (MAXT * BM)
#define NSTG   3

#define A_STG_B (BM * ASTR * 2)               // 18432 B
#define B_STG_B (BN * ASTR * 2)               // 18432 B
#define STG_B   (A_STG_B + B_STG_B)           // 36864 B
#define SMEM_WT (NSTG * STG_B)                // 110592
#define SMEM_TOT (SMEM_WT + BM * 4)           // 111104 -> 2 CTAs/SM

// ---------------- device scratch ----------------
__device__ __align__(16) __half g_xh[MAXROWS * DIN];     // gathered fp16 activations (expert-sorted)
__device__ __align__(16) __half g_wh[NE * DOUT * DIN];   // fp16 weights
__device__ __align__(16) float  g_pair[NPAIR * DOUT];    // per-(token,expert) weighted outputs

__device__ int   g_cnt[NE];
__device__ int   g_pos[NE];
__device__ int   g_off[NE + 1];
__device__ float g_wt[NPAIR];
__device__ int   g_slot[NPAIR];
__device__ int   g_topi[NPAIR];
__device__ float g_topp[NPAIR];
__device__ int   g_tile_e[MAXT];
__device__ int   g_tile_r0[MAXT];
__device__ int   g_tile_rows[MAXT];
__device__ int   g_ntiles;
__device__ int   g_done;

// ---------------- helpers ----------------
__device__ __forceinline__ void cpa16(uint32_t dst, const void* src) {
    asm volatile("cp.async.cg.shared.global [%0], [%1], 16;\n" :: "r"(dst), "l"(src));
}
__device__ __forceinline__ void ldsm_x4(uint32_t* r, uint32_t addr) {
    asm volatile("ldmatrix.sync.aligned.m8n8.x4.shared.b16 {%0,%1,%2,%3}, [%4];"
                 : "=r"(r[0]), "=r"(r[1]), "=r"(r[2]), "=r"(r[3]) : "r"(addr));
}
__device__ __forceinline__ void mma16816(float* c, const uint32_t* a, const uint32_t* b) {
    asm volatile(
        "mma.sync.aligned.m16n8k16.row.col.f32.f16.f16.f32 "
        "{%0,%1,%2,%3}, {%4,%5,%6,%7}, {%8,%9}, {%0,%1,%2,%3};\n"
        : "+f"(c[0]), "+f"(c[1]), "+f"(c[2]), "+f"(c[3])
        : "r"(a[0]), "r"(a[1]), "r"(a[2]), "r"(a[3]), "r"(b[0]), "r"(b[1]));
}
__device__ __forceinline__ uint32_t pack2h(float a, float b) {
    __half2 h = __floats2half2_rn(a, b);
    return *(uint32_t*)&h;
}

// ---------------- launch 0: fp32->fp16 of w (+ counter reset) ----------------
__global__ void convert_w_kernel(const float* __restrict__ w) {
    if (blockIdx.x == 0 && threadIdx.x < NE) {
        g_cnt[threadIdx.x] = 0;
        g_pos[threadIdx.x] = 0;
    }
    size_t idx = (size_t)blockIdx.x * 256 + threadIdx.x;
    const float4* ws = (const float4*)w;
    float4 a = ws[idx * 2], b = ws[idx * 2 + 1];
    uint4 o;
    o.x = pack2h(a.x, a.y);  o.y = pack2h(a.z, a.w);
    o.z = pack2h(b.x, b.y);  o.w = pack2h(b.z, b.w);
    ((uint4*)g_wh)[idx] = o;
}

// ---------------- launch 1: gating + last-block scan ----------------
__global__ void gate_kernel(const float* __restrict__ x,
                            const float* __restrict__ gw,
                            const float* __restrict__ gb) {
    int t = blockIdx.x;
    const float* xr = x + (size_t)t * DIN;
    float acc[NE];
#pragma unroll
    for (int e = 0; e < NE; e++) acc[e] = 0.f;
    for (int k = threadIdx.x; k < DIN; k += 256) {
        float xv = xr[k];
#pragma unroll
        for (int e = 0; e < NE; e++) acc[e] += xv * gw[e * DIN + k];
    }
#pragma unroll
    for (int off = 16; off > 0; off >>= 1)
#pragma unroll
        for (int e = 0; e < NE; e++)
            acc[e] += __shfl_xor_sync(0xffffffffu, acc[e], off);

    __shared__ float red[NE][8];
    int warp = threadIdx.x >> 5, lane = threadIdx.x & 31;
    if (lane == 0)
#pragma unroll
        for (int e = 0; e < NE; e++) red[e][warp] = acc[e];
    __syncthreads();

    if (threadIdx.x == 0) {
        float lg[NE];
#pragma unroll
        for (int e = 0; e < NE; e++) {
            float s = 0.f;
#pragma unroll
            for (int w = 0; w < 8; w++) s += red[e][w];
            lg[e] = s + gb[e];
        }
        float m = lg[0];
#pragma unroll
        for (int e = 1; e < NE; e++) m = fmaxf(m, lg[e]);
        float pz[NE], Z = 0.f;
#pragma unroll
        for (int e = 0; e < NE; e++) { pz[e] = expf(lg[e] - m); Z += pz[e]; }
        int i1 = -1, i2 = -1; float m1 = -1.f, m2 = -1.f;
#pragma unroll
        for (int e = 0; e < NE; e++) {
            float p = pz[e];
            if (p > m1)      { m2 = m1; i2 = i1; m1 = p; i1 = e; }
            else if (p > m2) { m2 = p; i2 = e; }
        }
        float inv = 1.f / Z;
        g_topi[t * 2]     = i1;  g_topp[t * 2]     = m1 * inv;
        g_topi[t * 2 + 1] = i2;  g_topp[t * 2 + 1] = m2 * inv;
        atomicAdd(&g_cnt[i1], 1);
        atomicAdd(&g_cnt[i2], 1);

        __threadfence();
        int old = atomicAdd(&g_done, 1);
        if (old == NTOK - 1) {
            int off = 0, nt = 0;
            for (int e = 0; e < NE; e++) {
                g_off[e] = off;
                int c = g_cnt[e];
                for (int r = 0; r < c; r += BM) {
                    g_tile_e[nt] = e;
                    g_tile_r0[nt] = off + r;
                    g_tile_rows[nt] = (c - r < BM) ? (c - r) : BM;
                    nt++;
                }
                off += c;
            }
            g_off[NE] = off;
            g_ntiles = nt;
            g_done = 0;
            __threadfence();
        }
    }
}

// ---------------- launch 2: scatter + gather + fp32->fp16 ----------------
__global__ void scatter_gather_kernel(const float* __restrict__ x) {
    int t = blockIdx.x;
    __shared__ int s_slot[2];
    if (threadIdx.x == 0) {
#pragma unroll
        for (int k = 0; k < 2; k++) {
            int e = g_topi[t * 2 + k];
            float p = g_topp[t * 2 + k];
            int pos = atomicAdd(&g_pos[e], 1);
            int slot = g_off[e] + pos;
            g_wt[slot]        = p;
            g_slot[t * 2 + k] = slot;
            s_slot[k] = slot;
        }
    }
    __syncthreads();
    int s0 = s_slot[0], s1 = s_slot[1];

    const float4* xs = (const float4*)(x + (size_t)t * DIN);
    int i = threadIdx.x;
    float4 a = xs[i * 2], b = xs[i * 2 + 1];
    uint4 o;
    o.x = pack2h(a.x, a.y);  o.y = pack2h(a.z, a.w);
    o.z = pack2h(b.x, b.y);  o.w = pack2h(b.z, b.w);
    ((uint4*)(g_xh + (size_t)s0 * DIN))[i] = o;
    ((uint4*)(g_xh + (size_t)s1 * DIN))[i] = o;
}

// ---------------- launch 3: grouped GEMM ----------------
// 128x128 tile, 4 warps (warp tile 64x64), 3-stage cp.async ring, 2 CTAs/SM
extern __shared__ char dsm[];

__global__ __launch_bounds__(128, 2) void gemm_kernel(const float* __restrict__ bias) {
    int mt = blockIdx.y;
    if (mt >= g_ntiles) return;
    int e    = g_tile_e[mt];
    int row0 = g_tile_r0[mt];
    int rows = g_tile_rows[mt];
    int n0   = blockIdx.x * BN;

    float* wt_s = (float*)(dsm + SMEM_WT);

    int tid = threadIdx.x;
    int wid = tid >> 5, lane = tid & 31;
    wt_s[tid] = (tid < rows) ? g_wt[row0 + tid] : 0.f;

    // ---- producer addressing: each of 128 threads loads one FULL row (8 x 16B) of A and of B ----
    const __half* asrc = g_xh + (size_t)(row0 + tid) * DIN;
    const __half* bsrc = g_wh + ((size_t)e * DOUT + n0 + tid) * DIN;

    uint32_t aS[NSTG], bS[NSTG];
#pragma unroll
    for (int s = 0; s < NSTG; s++) {
        aS[s] = (uint32_t)__cvta_generic_to_shared(dsm + s * STG_B) + tid * (ASTR * 2);
        bS[s] = (uint32_t)__cvta_generic_to_shared(dsm + s * STG_B + A_STG_B) + tid * (ASTR * 2);
    }

    auto issue = [&](int step) {
        int buf = step % NSTG;
        const __half* as = asrc + step * BK;
        const __half* bs = bsrc + step * BK;
#pragma unroll
        for (int i = 0; i < 8; i++) cpa16(aS[buf] + i * 16, as + i * 8);
#pragma unroll
        for (int j = 0; j < 8; j++) cpa16(bS[buf] + j * 16, bs + j * 8);
    };

    // ---- compute addressing (ldmatrix): 2x2 warp grid, warp tile 64x64 ----
    int wm = wid >> 1, wn = wid & 1;
    int a_r = lane & 15, a_k = (lane >> 4) * 8;
    int b_r = ((lane >> 4) * 8) + (lane & 7), b_k = ((lane >> 3) & 1) * 8;

    uint32_t aL[NSTG][4], bL[NSTG][4];
#pragma unroll
    for (int s = 0; s < NSTG; s++) {
        char* Ab = dsm + s * STG_B;
        char* Bb = dsm + s * STG_B + A_STG_B;
#pragma unroll
        for (int im = 0; im < 4; im++)
            aL[s][im] = (uint32_t)__cvta_generic_to_shared(
                Ab + ((wm * 64 + im * 16 + a_r) * ASTR + a_k) * 2);
#pragma unroll
        for (int ip = 0; ip < 4; ip++)   // covers in = 2*ip, 2*ip+1 (64 n per warp)
            bL[s][ip] = (uint32_t)__cvta_generic_to_shared(
                Bb + ((wn * 64 + ip * 16 + b_r) * ASTR + b_k) * 2);
    }

    float acc[4][8][4];
#pragma unroll
    for (int im = 0; im < 4; im++)
#pragma unroll
        for (int in = 0; in < 8; in++)
#pragma unroll
            for (int j = 0; j < 4; j++) acc[im][in][j] = 0.f;

    // ---- prologue: 2 stages in flight ----
    issue(0);
    asm volatile("cp.async.commit_group;\n");
    issue(1);
    asm volatile("cp.async.commit_group;\n");

    for (int s = 0; s < KSTEPS; s++) {
        asm volatile("cp.async.wait_group 1;\n");
        __syncthreads();
        if (s + 2 < KSTEPS) issue(s + 2);
        asm volatile("cp.async.commit_group;\n");

        int buf = s % NSTG;
#pragma unroll
        for (int kk = 0; kk < BK; kk += 16) {
            uint32_t a[4][4], b[8][2];
#pragma unroll
            for (int im = 0; im < 4; im++)
                ldsm_x4(a[im], aL[buf][im] + kk * 2);
#pragma unroll
            for (int ip = 0; ip < 4; ip++) {
                uint32_t r[4];
                ldsm_x4(r, bL[buf][ip] + kk * 2);
                b[2 * ip][0] = r[0];     b[2 * ip][1] = r[1];
                b[2 * ip + 1][0] = r[2]; b[2 * ip + 1][1] = r[3];
            }
#pragma unroll
            for (int im = 0; im < 4; im++)
#pragma unroll
                for (int in = 0; in < 8; in++)
                    mma16816(acc[im][in], a[im], b[in]);
        }
    }

    // ---- epilogue: weighted write to pair buffer ----
    int g = lane >> 2, tg = lane & 3;
#pragma unroll
    for (int im = 0; im < 4; im++) {
        int r0 = wm * 64 + im * 16 + g;
#pragma unroll
        for (int half = 0; half < 2; half++) {
            int r = r0 + half * 8;
            if (r < rows) {
                float w = wt_s[r];
                size_t ob = (size_t)(row0 + r) * DOUT + n0;
                const float* bp = bias + (size_t)e * DOUT + n0;
#pragma unroll
                for (int in = 0; in < 8; in++) {
                    int c = wn * 64 + in * 8 + tg * 2;
                    float2 v;
                    v.x = w * (acc[im][in][2 * half]     + bp[c]);
                    v.y = w * (acc[im][in][2 * half + 1] + bp[c + 1]);
                    *(float2*)(g_pair + ob + c) = v;
                }
            }
        }
    }
}

// ---------------- launch 4: combine ----------------
__global__ void combine_kernel(float* __restrict__ out) {
    int t = blockIdx.x;
    int s0 = g_slot[t * 2], s1 = g_slot[t * 2 + 1];
    const float4* p0 = (const float4*)(g_pair + (size_t)s0 * DOUT);
    const float4* p1 = (const float4*)(g_pair + (size_t)s1 * DOUT);
    float4* o = (float4*)(out + (size_t)t * DOUT);
#pragma unroll
    for (int k = 0; k < 2; k++) {
        int i = threadIdx.x + k * 256;
        float4 a = p0[i], b = p1[i];
        float4 v;
        v.x = a.x + b.x;  v.y = a.y + b.y;  v.z = a.z + b.z;  v.w = a.w + b.w;
        o[i] = v;
    }
}

// ---------------- launch ----------------
extern "C" void kernel_launch(void* const* d_in, const int* in_sizes, int n_in,
                              void* d_out, int out_size) {
    const float* x  = (const float*)d_in[0];
    const float* ew = (const float*)d_in[1];
    const float* eb = (const float*)d_in[2];
    const float* gw = (const float*)d_in[3];
    const float* gb = (const float*)d_in[4];
    float* out = (float*)d_out;

    cudaFuncSetAttribute(gemm_kernel, cudaFuncAttributeMaxDynamicSharedMemorySize, SMEM_TOT);

    convert_w_kernel<<<NE * DOUT * DIN / (256 * 8), 256>>>(ew);
    gate_kernel<<<NTOK, 256>>>(x, gw, gb);
    scatter_gather_kernel<<<NTOK, 256>>>(x);
    gemm_kernel<<<dim3(NTILE, MAXT), 128, SMEM_TOT>>>(eb);   // profiled slot
    combine_kernel<<<NTOK, 256>>>(out);
}

// round 12
// speedup vs baseline: 1.6837x; 1.6837x over previous
#include <cuda_runtime.h>
#include <cuda_fp16.h>
#include <stdint.h>

// ---------------- problem constants ----------------
#define NE    8
#define DIN   2048
#define DOUT  2048
#define NTOK  8192
#define NPAIR (NTOK * 2)

// ---------------- GEMM tiling ----------------
#define BM     128
#define BN     128
#define BK     64
#define ASTR   72                  // padded smem row stride (halves); conflict-free LDSM
#define KSTEPS (DIN / BK)          // 32
#define NTILE  (DOUT / BN)         // 16
#define MAXT   136
#define MAXROWS (MAXT * BM)
#define NSTG   3

#define A_STG_B (BM * ASTR * 2)               // 18432 B
#define B_STG_B (BN * ASTR * 2)               // 18432 B
#define STG_B   (A_STG_B + B_STG_B)           // 36864 B
#define SMEM_WT (NSTG * STG_B)                // 110592
#define SMEM_TOT (SMEM_WT + BM * 4)           // 111104 -> 2 CTAs/SM

// ---------------- device scratch ----------------
__device__ __align__(16) __half g_xh[MAXROWS * DIN];     // gathered fp16 activations (expert-sorted)
__device__ __align__(16) __half g_wh[NE * DOUT * DIN];   // fp16 weights
__device__ __align__(16) float  g_pair[NPAIR * DOUT];    // per-(token,expert) weighted outputs

__device__ int   g_cnt[NE];
__device__ int   g_pos[NE];
__device__ int   g_off[NE + 1];
__device__ float g_wt[NPAIR];
__device__ int   g_slot[NPAIR];
__device__ int   g_topi[NPAIR];
__device__ float g_topp[NPAIR];
__device__ int   g_tile_e[MAXT];
__device__ int   g_tile_r0[MAXT];
__device__ int   g_tile_rows[MAXT];
__device__ int   g_ntiles;
__device__ int   g_done;

// ---------------- helpers ----------------
__device__ __forceinline__ void cpa16(uint32_t dst, const void* src) {
    asm volatile("cp.async.cg.shared.global [%0], [%1], 16;\n" :: "r"(dst), "l"(src));
}
__device__ __forceinline__ void ldsm_x4(uint32_t* r, uint32_t addr) {
    asm volatile("ldmatrix.sync.aligned.m8n8.x4.shared.b16 {%0,%1,%2,%3}, [%4];"
                 : "=r"(r[0]), "=r"(r[1]), "=r"(r[2]), "=r"(r[3]) : "r"(addr));
}
__device__ __forceinline__ void mma16816(float* c, const uint32_t* a, const uint32_t* b) {
    asm volatile(
        "mma.sync.aligned.m16n8k16.row.col.f32.f16.f16.f32 "
        "{%0,%1,%2,%3}, {%4,%5,%6,%7}, {%8,%9}, {%0,%1,%2,%3};\n"
        : "+f"(c[0]), "+f"(c[1]), "+f"(c[2]), "+f"(c[3])
        : "r"(a[0]), "r"(a[1]), "r"(a[2]), "r"(a[3]), "r"(b[0]), "r"(b[1]));
}
__device__ __forceinline__ uint32_t pack2h(float a, float b) {
    __half2 h = __floats2half2_rn(a, b);
    return *(uint32_t*)&h;
}

// ---------------- launch 0: fp32->fp16 of w (+ counter reset) ----------------
__global__ void convert_w_kernel(const float* __restrict__ w) {
    if (blockIdx.x == 0 && threadIdx.x < NE) {
        g_cnt[threadIdx.x] = 0;
        g_pos[threadIdx.x] = 0;
    }
    size_t idx = (size_t)blockIdx.x * 256 + threadIdx.x;
    const float4* ws = (const float4*)w;
    float4 a = ws[idx * 2], b = ws[idx * 2 + 1];
    uint4 o;
    o.x = pack2h(a.x, a.y);  o.y = pack2h(a.z, a.w);
    o.z = pack2h(b.x, b.y);  o.w = pack2h(b.z, b.w);
    ((uint4*)g_wh)[idx] = o;
}

// ---------------- launch 1: gating + last-block scan ----------------
__global__ void gate_kernel(const float* __restrict__ x,
                            const float* __restrict__ gw,
                            const float* __restrict__ gb) {
    int t = blockIdx.x;
    const float* xr = x + (size_t)t * DIN;
    float acc[NE];
#pragma unroll
    for (int e = 0; e < NE; e++) acc[e] = 0.f;
    for (int k = threadIdx.x; k < DIN; k += 256) {
        float xv = xr[k];
#pragma unroll
        for (int e = 0; e < NE; e++) acc[e] += xv * gw[e * DIN + k];
    }
#pragma unroll
    for (int off = 16; off > 0; off >>= 1)
#pragma unroll
        for (int e = 0; e < NE; e++)
            acc[e] += __shfl_xor_sync(0xffffffffu, acc[e], off);

    __shared__ float red[NE][8];
    int warp = threadIdx.x >> 5, lane = threadIdx.x & 31;
    if (lane == 0)
#pragma unroll
        for (int e = 0; e < NE; e++) red[e][warp] = acc[e];
    __syncthreads();

    if (threadIdx.x == 0) {
        float lg[NE];
#pragma unroll
        for (int e = 0; e < NE; e++) {
            float s = 0.f;
#pragma unroll
            for (int w = 0; w < 8; w++) s += red[e][w];
            lg[e] = s + gb[e];
        }
        float m = lg[0];
#pragma unroll
        for (int e = 1; e < NE; e++) m = fmaxf(m, lg[e]);
        float pz[NE], Z = 0.f;
#pragma unroll
        for (int e = 0; e < NE; e++) { pz[e] = expf(lg[e] - m); Z += pz[e]; }
        int i1 = -1, i2 = -1; float m1 = -1.f, m2 = -1.f;
#pragma unroll
        for (int e = 0; e < NE; e++) {
            float p = pz[e];
            if (p > m1)      { m2 = m1; i2 = i1; m1 = p; i1 = e; }
            else if (p > m2) { m2 = p; i2 = e; }
        }
        float inv = 1.f / Z;
        g_topi[t * 2]     = i1;  g_topp[t * 2]     = m1 * inv;
        g_topi[t * 2 + 1] = i2;  g_topp[t * 2 + 1] = m2 * inv;
        atomicAdd(&g_cnt[i1], 1);
        atomicAdd(&g_cnt[i2], 1);

        __threadfence();
        int old = atomicAdd(&g_done, 1);
        if (old == NTOK - 1) {
            int off = 0, nt = 0;
            for (int e = 0; e < NE; e++) {
                g_off[e] = off;
                int c = g_cnt[e];
                for (int r = 0; r < c; r += BM) {
                    g_tile_e[nt] = e;
                    g_tile_r0[nt] = off + r;
                    g_tile_rows[nt] = (c - r < BM) ? (c - r) : BM;
                    nt++;
                }
                off += c;
            }
            g_off[NE] = off;
            g_ntiles = nt;
            g_done = 0;
            __threadfence();
        }
    }
}

// ---------------- launch 2: scatter + gather + fp32->fp16 ----------------
__global__ void scatter_gather_kernel(const float* __restrict__ x) {
    int t = blockIdx.x;
    __shared__ int s_slot[2];
    if (threadIdx.x == 0) {
#pragma unroll
        for (int k = 0; k < 2; k++) {
            int e = g_topi[t * 2 + k];
            float p = g_topp[t * 2 + k];
            int pos = atomicAdd(&g_pos[e], 1);
            int slot = g_off[e] + pos;
            g_wt[slot]        = p;
            g_slot[t * 2 + k] = slot;
            s_slot[k] = slot;
        }
    }
    __syncthreads();
    int s0 = s_slot[0], s1 = s_slot[1];

    const float4* xs = (const float4*)(x + (size_t)t * DIN);
    int i = threadIdx.x;
    float4 a = xs[i * 2], b = xs[i * 2 + 1];
    uint4 o;
    o.x = pack2h(a.x, a.y);  o.y = pack2h(a.z, a.w);
    o.z = pack2h(b.x, b.y);  o.w = pack2h(b.z, b.w);
    ((uint4*)(g_xh + (size_t)s0 * DIN))[i] = o;
    ((uint4*)(g_xh + (size_t)s1 * DIN))[i] = o;
}

// ---------------- launch 3: grouped GEMM ----------------
// R3 core: 128x128 tile, 8 warps (warp tile 64x32), 2 CTAs/SM — now with 3-stage ring
extern __shared__ char dsm[];

__global__ __launch_bounds__(256, 2) void gemm_kernel(const float* __restrict__ bias) {
    int mt = blockIdx.y;
    if (mt >= g_ntiles) return;
    int e    = g_tile_e[mt];
    int row0 = g_tile_r0[mt];
    int rows = g_tile_rows[mt];
    int n0   = blockIdx.x * BN;

    float* wt_s = (float*)(dsm + SMEM_WT);

    int tid = threadIdx.x;
    int wid = tid >> 5, lane = tid & 31;
    if (tid < BM) wt_s[tid] = (tid < rows) ? g_wt[row0 + tid] : 0.f;

    // ---- producer addressing: thread t loads row t>>1, 4 x 16B chunks ----
    int lrow = tid >> 1;
    int lch  = (tid & 1) * 4;
    const __half* asrc = g_xh + (size_t)(row0 + lrow) * DIN + lch * 8;
    const __half* bsrc = g_wh + ((size_t)e * DOUT + n0 + lrow) * DIN + lch * 8;

    uint32_t aS[NSTG], bS[NSTG];
#pragma unroll
    for (int s = 0; s < NSTG; s++) {
        aS[s] = (uint32_t)__cvta_generic_to_shared(dsm + s * STG_B) +
                (lrow * ASTR + lch * 8) * 2;
        bS[s] = (uint32_t)__cvta_generic_to_shared(dsm + s * STG_B + A_STG_B) +
                (lrow * ASTR + lch * 8) * 2;
    }

    auto issue = [&](int step) {
        int buf = step % NSTG;
        const __half* as = asrc + step * BK;
        const __half* bs = bsrc + step * BK;
#pragma unroll
        for (int i = 0; i < 4; i++) {
            cpa16(aS[buf] + i * 16, as + i * 8);
            cpa16(bS[buf] + i * 16, bs + i * 8);
        }
    };

    // ---- compute addressing (ldmatrix): 2x4 warp grid, warp tile 64x32 ----
    int wm = wid >> 2, wn = wid & 3;
    int a_r = lane & 15, a_k = (lane >> 4) * 8;
    int b_r = ((lane >> 4) * 8) + (lane & 7), b_k = ((lane >> 3) & 1) * 8;

    uint32_t aL[NSTG][4], bL[NSTG][2];
#pragma unroll
    for (int s = 0; s < NSTG; s++) {
        char* Ab = dsm + s * STG_B;
        char* Bb = dsm + s * STG_B + A_STG_B;
#pragma unroll
        for (int im = 0; im < 4; im++)
            aL[s][im] = (uint32_t)__cvta_generic_to_shared(
                Ab + ((wm * 64 + im * 16 + a_r) * ASTR + a_k) * 2);
#pragma unroll
        for (int ip = 0; ip < 2; ip++)
            bL[s][ip] = (uint32_t)__cvta_generic_to_shared(
                Bb + ((wn * 32 + ip * 16 + b_r) * ASTR + b_k) * 2);
    }

    float acc[4][4][4];
#pragma unroll
    for (int im = 0; im < 4; im++)
#pragma unroll
        for (int in = 0; in < 4; in++)
#pragma unroll
            for (int j = 0; j < 4; j++) acc[im][in][j] = 0.f;

    // ---- prologue: 2 stages in flight ----
    issue(0);
    asm volatile("cp.async.commit_group;\n");
    issue(1);
    asm volatile("cp.async.commit_group;\n");

    for (int s = 0; s < KSTEPS; s++) {
        asm volatile("cp.async.wait_group 1;\n");   // stage s complete; s+1 may be in flight
        __syncthreads();
        if (s + 2 < KSTEPS) issue(s + 2);
        asm volatile("cp.async.commit_group;\n");

        int buf = s % NSTG;
#pragma unroll
        for (int kk = 0; kk < BK; kk += 16) {
            uint32_t a[4][4], b[4][2];
#pragma unroll
            for (int im = 0; im < 4; im++)
                ldsm_x4(a[im], aL[buf][im] + kk * 2);
#pragma unroll
            for (int ip = 0; ip < 2; ip++) {
                uint32_t r[4];
                ldsm_x4(r, bL[buf][ip] + kk * 2);
                b[2 * ip][0] = r[0];     b[2 * ip][1] = r[1];
                b[2 * ip + 1][0] = r[2]; b[2 * ip + 1][1] = r[3];
            }
#pragma unroll
            for (int im = 0; im < 4; im++)
#pragma unroll
                for (int in = 0; in < 4; in++)
                    mma16816(acc[im][in], a[im], b[in]);
        }
    }

    // ---- epilogue: weighted write to pair buffer ----
    int g = lane >> 2, tg = lane & 3;
#pragma unroll
    for (int im = 0; im < 4; im++) {
        int r0 = wm * 64 + im * 16 + g;
#pragma unroll
        for (int half = 0; half < 2; half++) {
            int r = r0 + half * 8;
            if (r < rows) {
                float w = wt_s[r];
                size_t ob = (size_t)(row0 + r) * DOUT + n0;
                const float* bp = bias + (size_t)e * DOUT + n0;
#pragma unroll
                for (int in = 0; in < 4; in++) {
                    int c = wn * 32 + in * 8 + tg * 2;
                    float2 v;
                    v.x = w * (acc[im][in][2 * half]     + bp[c]);
                    v.y = w * (acc[im][in][2 * half + 1] + bp[c + 1]);
                    *(float2*)(g_pair + ob + c) = v;
                }
            }
        }
    }
}

// ---------------- launch 4: combine ----------------
__global__ void combine_kernel(float* __restrict__ out) {
    int t = blockIdx.x;
    int s0 = g_slot[t * 2], s1 = g_slot[t * 2 + 1];
    const float4* p0 = (const float4*)(g_pair + (size_t)s0 * DOUT);
    const float4* p1 = (const float4*)(g_pair + (size_t)s1 * DOUT);
    float4* o = (float4*)(out + (size_t)t * DOUT);
#pragma unroll
    for (int k = 0; k < 2; k++) {
        int i = threadIdx.x + k * 256;
        float4 a = p0[i], b = p1[i];
        float4 v;
        v.x = a.x + b.x;  v.y = a.y + b.y;  v.z = a.z + b.z;  v.w = a.w + b.w;
        o[i] = v;
    }
}

// ---------------- launch ----------------
extern "C" void kernel_launch(void* const* d_in, const int* in_sizes, int n_in,
                              void* d_out, int out_size) {
    const float* x  = (const float*)d_in[0];
    const float* ew = (const float*)d_in[1];
    const float* eb = (const float*)d_in[2];
    const float* gw = (const float*)d_in[3];
    const float* gb = (const float*)d_in[4];
    float* out = (float*)d_out;

    cudaFuncSetAttribute(gemm_kernel, cudaFuncAttributeMaxDynamicSharedMemorySize, SMEM_TOT);

    convert_w_kernel<<<NE * DOUT * DIN / (256 * 8), 256>>>(ew);
    gate_kernel<<<NTOK, 256>>>(x, gw, gb);
    scatter_gather_kernel<<<NTOK, 256>>>(x);
    gemm_kernel<<<dim3(NTILE, MAXT), 256, SMEM_TOT>>>(eb);   // profiled slot
    combine_kernel<<<NTOK, 256>>>(out);
}

// round 13
// speedup vs baseline: 1.7747x; 1.0541x over previous
#include <cuda_runtime.h>
#include <cuda_fp16.h>
#include <stdint.h>

// ---------------- problem constants ----------------
#define NE    8
#define DIN   2048
#define DOUT  2048
#define NTOK  8192
#define NPAIR (NTOK * 2)

// ---------------- GEMM tiling (R3-proven core) ----------------
#define BM     128
#define BN     128
#define BK     64
#define ASTR   72                  // padded smem row stride (halves); conflict-free LDSM
#define KSTEPS (DIN / BK)          // 32
#define NTILE  (DOUT / BN)         // 16
#define MAXT   136

#define A_STG_B (BM * ASTR * 2)               // 18432 B
#define B_STG_B (BN * ASTR * 2)               // 18432 B
#define STG_B   (A_STG_B + B_STG_B)           // 36864 B
#define SMEM_WT (2 * STG_B)                   // 73728
#define SMEM_TOK (SMEM_WT + BM * 4)
#define SMEM_TOT (SMEM_TOK + BM * 4)          // 74752 -> 2 CTAs/SM

// ---------------- device scratch ----------------
__device__ __align__(16) __half g_xh[NTOK * DIN];        // fp16 activations, TOKEN order
__device__ __align__(16) __half g_wh[NE * DOUT * DIN];   // fp16 weights

__device__ int   g_cnt[NE];
__device__ int   g_pos[NE];
__device__ int   g_off[NE + 1];
__device__ int   g_tok[NPAIR];      // slot -> token
__device__ float g_wt[NPAIR];       // slot -> gate prob
__device__ int   g_topi[NPAIR];
__device__ float g_topp[NPAIR];
__device__ int   g_tile_e[MAXT];
__device__ int   g_tile_r0[MAXT];
__device__ int   g_tile_rows[MAXT];
__device__ int   g_ntiles;
__device__ int   g_done;

// ---------------- helpers ----------------
__device__ __forceinline__ void cpa16(uint32_t dst, const void* src) {
    asm volatile("cp.async.cg.shared.global [%0], [%1], 16;\n" :: "r"(dst), "l"(src));
}
__device__ __forceinline__ void ldsm_x4(uint32_t* r, uint32_t addr) {
    asm volatile("ldmatrix.sync.aligned.m8n8.x4.shared.b16 {%0,%1,%2,%3}, [%4];"
                 : "=r"(r[0]), "=r"(r[1]), "=r"(r[2]), "=r"(r[3]) : "r"(addr));
}
__device__ __forceinline__ void mma16816(float* c, const uint32_t* a, const uint32_t* b) {
    asm volatile(
        "mma.sync.aligned.m16n8k16.row.col.f32.f16.f16.f32 "
        "{%0,%1,%2,%3}, {%4,%5,%6,%7}, {%8,%9}, {%0,%1,%2,%3};\n"
        : "+f"(c[0]), "+f"(c[1]), "+f"(c[2]), "+f"(c[3])
        : "r"(a[0]), "r"(a[1]), "r"(a[2]), "r"(a[3]), "r"(b[0]), "r"(b[1]));
}
__device__ __forceinline__ uint32_t pack2h(float a, float b) {
    __half2 h = __floats2half2_rn(a, b);
    return *(uint32_t*)&h;
}

// ---------------- launch 0: fp32->fp16 of w (+ counter reset) ----------------
__global__ void convert_w_kernel(const float* __restrict__ w) {
    if (blockIdx.x == 0 && threadIdx.x < NE) {
        g_cnt[threadIdx.x] = 0;
        g_pos[threadIdx.x] = 0;
    }
    size_t idx = (size_t)blockIdx.x * 256 + threadIdx.x;   // 8 elems per thread
    const float4* ws = (const float4*)w;
    float4 a = ws[idx * 2], b = ws[idx * 2 + 1];
    uint4 o;
    o.x = pack2h(a.x, a.y);  o.y = pack2h(a.z, a.w);
    o.z = pack2h(b.x, b.y);  o.w = pack2h(b.z, b.w);
    ((uint4*)g_wh)[idx] = o;
}

// ---------------- launch 1: gating + x fp16 convert + out zero + last-block scan ----------------
__global__ void gate_kernel(const float* __restrict__ x,
                            const float* __restrict__ gw,
                            const float* __restrict__ gb,
                            float* __restrict__ out) {
    int t = blockIdx.x;
    const float* xr = x + (size_t)t * DIN;

    // vectorized: convert this token's row to fp16 (token order) + zero out row
    {
        int i = threadIdx.x;                              // 256 threads x 8 elems
        const float4* xs = (const float4*)xr;
        float4 a = xs[i * 2], b = xs[i * 2 + 1];
        uint4 o;
        o.x = pack2h(a.x, a.y);  o.y = pack2h(a.z, a.w);
        o.z = pack2h(b.x, b.y);  o.w = pack2h(b.z, b.w);
        ((uint4*)(g_xh + (size_t)t * DIN))[i] = o;
        float4 z = make_float4(0.f, 0.f, 0.f, 0.f);
        float4* o4 = (float4*)(out + (size_t)t * DOUT);
        o4[i * 2]     = z;
        o4[i * 2 + 1] = z;
    }

    float acc[NE];
#pragma unroll
    for (int e = 0; e < NE; e++) acc[e] = 0.f;
    for (int k = threadIdx.x; k < DIN; k += 256) {
        float xv = xr[k];
#pragma unroll
        for (int e = 0; e < NE; e++) acc[e] += xv * gw[e * DIN + k];
    }
#pragma unroll
    for (int off = 16; off > 0; off >>= 1)
#pragma unroll
        for (int e = 0; e < NE; e++)
            acc[e] += __shfl_xor_sync(0xffffffffu, acc[e], off);

    __shared__ float red[NE][8];
    int warp = threadIdx.x >> 5, lane = threadIdx.x & 31;
    if (lane == 0)
#pragma unroll
        for (int e = 0; e < NE; e++) red[e][warp] = acc[e];
    __syncthreads();

    if (threadIdx.x == 0) {
        float lg[NE];
#pragma unroll
        for (int e = 0; e < NE; e++) {
            float s = 0.f;
#pragma unroll
            for (int w = 0; w < 8; w++) s += red[e][w];
            lg[e] = s + gb[e];
        }
        float m = lg[0];
#pragma unroll
        for (int e = 1; e < NE; e++) m = fmaxf(m, lg[e]);
        float pz[NE], Z = 0.f;
#pragma unroll
        for (int e = 0; e < NE; e++) { pz[e] = expf(lg[e] - m); Z += pz[e]; }
        int i1 = -1, i2 = -1; float m1 = -1.f, m2 = -1.f;
#pragma unroll
        for (int e = 0; e < NE; e++) {
            float p = pz[e];
            if (p > m1)      { m2 = m1; i2 = i1; m1 = p; i1 = e; }
            else if (p > m2) { m2 = p; i2 = e; }
        }
        float inv = 1.f / Z;
        g_topi[t * 2]     = i1;  g_topp[t * 2]     = m1 * inv;
        g_topi[t * 2 + 1] = i2;  g_topp[t * 2 + 1] = m2 * inv;
        atomicAdd(&g_cnt[i1], 1);
        atomicAdd(&g_cnt[i2], 1);

        __threadfence();
        int old = atomicAdd(&g_done, 1);
        if (old == NTOK - 1) {                 // last block: 8-expert scan + tile table
            int off = 0, nt = 0;
            for (int e = 0; e < NE; e++) {
                g_off[e] = off;
                int c = g_cnt[e];
                for (int r = 0; r < c; r += BM) {
                    g_tile_e[nt] = e;
                    g_tile_r0[nt] = off + r;
                    g_tile_rows[nt] = (c - r < BM) ? (c - r) : BM;
                    nt++;
                }
                off += c;
            }
            g_off[NE] = off;
            g_ntiles = nt;
            g_done = 0;                        // reset for next graph replay
            __threadfence();
        }
    }
}

// ---------------- launch 2: scatter (slot assignment only; tiny) ----------------
__global__ void scatter_kernel() {
    int t = blockIdx.x * blockDim.x + threadIdx.x;
    if (t >= NTOK) return;
#pragma unroll
    for (int k = 0; k < 2; k++) {
        int e = g_topi[t * 2 + k];
        float p = g_topp[t * 2 + k];
        int pos = atomicAdd(&g_pos[e], 1);
        int slot = g_off[e] + pos;
        g_tok[slot] = t;
        g_wt[slot]  = p;
    }
}

// ---------------- launch 3: grouped GEMM (R3 core + token indirection + atomic epilogue) ----------------
extern __shared__ char dsm[];

__global__ __launch_bounds__(256, 2) void gemm_kernel(const float* __restrict__ bias,
                                                      float* __restrict__ out) {
    int mt = blockIdx.y;
    if (mt >= g_ntiles) return;
    int e    = g_tile_e[mt];
    int row0 = g_tile_r0[mt];
    int rows = g_tile_rows[mt];
    int n0   = blockIdx.x * BN;

    float* wt_s = (float*)(dsm + SMEM_WT);
    int*   tok_s = (int*)(dsm + SMEM_TOK);

    int tid = threadIdx.x;
    int wid = tid >> 5, lane = tid & 31;
    if (tid < BM) {
        tok_s[tid] = (tid < rows) ? g_tok[row0 + tid] : 0;
        wt_s[tid]  = (tid < rows) ? g_wt[row0 + tid] : 0.f;
    }
    __syncthreads();

    // ---- producer addressing: thread t loads token row tok_s[t>>1], 4 x 16B chunks ----
    int lrow = tid >> 1;
    int lch  = (tid & 1) * 4;
    const __half* asrc = g_xh + (size_t)tok_s[lrow] * DIN + lch * 8;
    const __half* bsrc = g_wh + ((size_t)e * DOUT + n0 + lrow) * DIN + lch * 8;

    uint32_t aS[2], bS[2];
#pragma unroll
    for (int s = 0; s < 2; s++) {
        aS[s] = (uint32_t)__cvta_generic_to_shared(dsm + s * STG_B) +
                (lrow * ASTR + lch * 8) * 2;
        bS[s] = (uint32_t)__cvta_generic_to_shared(dsm + s * STG_B + A_STG_B) +
                (lrow * ASTR + lch * 8) * 2;
    }

    auto issue = [&](int step, int buf) {
        const __half* as = asrc + step * BK;
        const __half* bs = bsrc + step * BK;
#pragma unroll
        for (int i = 0; i < 4; i++) {
            cpa16(aS[buf] + i * 16, as + i * 8);
            cpa16(bS[buf] + i * 16, bs + i * 8);
        }
    };

    // ---- compute addressing (ldmatrix): 2x4 warp grid, warp tile 64x32 ----
    int wm = wid >> 2, wn = wid & 3;
    int a_r = lane & 15, a_k = (lane >> 4) * 8;
    int b_r = ((lane >> 4) * 8) + (lane & 7), b_k = ((lane >> 3) & 1) * 8;

    uint32_t aL[2][4], bL[2][2];
#pragma unroll
    for (int s = 0; s < 2; s++) {
        char* Ab = dsm + s * STG_B;
        char* Bb = dsm + s * STG_B + A_STG_B;
#pragma unroll
        for (int im = 0; im < 4; im++)
            aL[s][im] = (uint32_t)__cvta_generic_to_shared(
                Ab + ((wm * 64 + im * 16 + a_r) * ASTR + a_k) * 2);
#pragma unroll
        for (int ip = 0; ip < 2; ip++)
            bL[s][ip] = (uint32_t)__cvta_generic_to_shared(
                Bb + ((wn * 32 + ip * 16 + b_r) * ASTR + b_k) * 2);
    }

    float acc[4][4][4];
#pragma unroll
    for (int im = 0; im < 4; im++)
#pragma unroll
        for (int in = 0; in < 4; in++)
#pragma unroll
            for (int j = 0; j < 4; j++) acc[im][in][j] = 0.f;

    // ---- R3-proven 2-stage loop ----
    issue(0, 0);
    asm volatile("cp.async.commit_group;\n");
    int cur = 0;
    for (int s = 0; s < KSTEPS; s++) {
        if (s + 1 < KSTEPS) issue(s + 1, cur ^ 1);
        asm volatile("cp.async.commit_group;\n");
        asm volatile("cp.async.wait_group 1;\n");
        __syncthreads();

#pragma unroll
        for (int kk = 0; kk < BK; kk += 16) {
            uint32_t a[4][4], b[4][2];
#pragma unroll
            for (int im = 0; im < 4; im++)
                ldsm_x4(a[im], aL[cur][im] + kk * 2);
#pragma unroll
            for (int ip = 0; ip < 2; ip++) {
                uint32_t r[4];
                ldsm_x4(r, bL[cur][ip] + kk * 2);
                b[2 * ip][0] = r[0];     b[2 * ip][1] = r[1];
                b[2 * ip + 1][0] = r[2]; b[2 * ip + 1][1] = r[3];
            }
#pragma unroll
            for (int im = 0; im < 4; im++)
#pragma unroll
                for (int in = 0; in < 4; in++)
                    mma16816(acc[im][in], a[im], b[in]);
        }
        __syncthreads();
        cur ^= 1;
    }

    // ---- epilogue: atomic accumulate weighted result directly into out ----
    // each out element receives exactly 2 commutative fp32 adds -> deterministic
    int g = lane >> 2, tg = lane & 3;
#pragma unroll
    for (int im = 0; im < 4; im++) {
        int r0 = wm * 64 + im * 16 + g;
#pragma unroll
        for (int half = 0; half < 2; half++) {
            int r = r0 + half * 8;
            if (r < rows) {
                int t = tok_s[r];
                float w = wt_s[r];
                float* orow = out + (size_t)t * DOUT + n0;
                const float* bp = bias + (size_t)e * DOUT + n0;
#pragma unroll
                for (int in = 0; in < 4; in++) {
                    int c = wn * 32 + in * 8 + tg * 2;
                    atomicAdd(&orow[c],     w * (acc[im][in][2 * half]     + bp[c]));
                    atomicAdd(&orow[c + 1], w * (acc[im][in][2 * half + 1] + bp[c + 1]));
                }
            }
        }
    }
}

// ---------------- launch ----------------
extern "C" void kernel_launch(void* const* d_in, const int* in_sizes, int n_in,
                              void* d_out, int out_size) {
    const float* x  = (const float*)d_in[0];
    const float* ew = (const float*)d_in[1];
    const float* eb = (const float*)d_in[2];
    const float* gw = (const float*)d_in[3];
    const float* gb = (const float*)d_in[4];
    float* out = (float*)d_out;

    cudaFuncSetAttribute(gemm_kernel, cudaFuncAttributeMaxDynamicSharedMemorySize, SMEM_TOT);

    convert_w_kernel<<<NE * DOUT * DIN / (256 * 8), 256>>>(ew);
    gate_kernel<<<NTOK, 256>>>(x, gw, gb, out);
    scatter_kernel<<<(NTOK + 255) / 256, 256>>>();
    gemm_kernel<<<dim3(NTILE, MAXT), 256, SMEM_TOT>>>(eb, out);   // profiled slot
}

// round 14
// speedup vs baseline: 1.7978x; 1.0130x over previous
#include <cuda_runtime.h>
#include <cuda_fp16.h>
#include <stdint.h>

// ---------------- problem constants ----------------
#define NE    8
#define DIN   2048
#define DOUT  2048
#define NTOK  8192
#define NPAIR (NTOK * 2)
#define WBLKS (NE * DOUT * DIN / (256 * 8))   // 16384 convert-W blocks

// ---------------- GEMM tiling (R3-proven core) ----------------
#define BM     128
#define BN     128
#define BK     64
#define ASTR   72
#define KSTEPS (DIN / BK)          // 32
#define NTILE  (DOUT / BN)         // 16
#define MAXT   136

#define A_STG_B (BM * ASTR * 2)
#define B_STG_B (BN * ASTR * 2)
#define STG_B   (A_STG_B + B_STG_B)
#define SMEM_WT (2 * STG_B)
#define SMEM_TOK (SMEM_WT + BM * 4)
#define SMEM_TOT (SMEM_TOK + BM * 4)          // 74752 -> 2 CTAs/SM

// ---------------- device scratch ----------------
__device__ __align__(16) __half g_xh[NTOK * DIN];        // fp16 activations, TOKEN order
__device__ __align__(16) __half g_wh[NE * DOUT * DIN];   // fp16 weights

__device__ int   g_cnt[NE];         // zero at entry; scan resets after read
__device__ int   g_pos[NE];         // zero at entry; reset_pos resets after scatter
__device__ int   g_off[NE + 1];
__device__ int   g_tok[NPAIR];
__device__ float g_wt[NPAIR];
__device__ int   g_topi[NPAIR];
__device__ float g_topp[NPAIR];
__device__ int   g_tile_e[MAXT];
__device__ int   g_tile_r0[MAXT];
__device__ int   g_tile_rows[MAXT];
__device__ int   g_ntiles;
__device__ int   g_done;            // self-resetting

// ---------------- helpers ----------------
__device__ __forceinline__ void cpa16(uint32_t dst, const void* src) {
    asm volatile("cp.async.cg.shared.global [%0], [%1], 16;\n" :: "r"(dst), "l"(src));
}
__device__ __forceinline__ void ldsm_x4(uint32_t* r, uint32_t addr) {
    asm volatile("ldmatrix.sync.aligned.m8n8.x4.shared.b16 {%0,%1,%2,%3}, [%4];"
                 : "=r"(r[0]), "=r"(r[1]), "=r"(r[2]), "=r"(r[3]) : "r"(addr));
}
__device__ __forceinline__ void mma16816(float* c, const uint32_t* a, const uint32_t* b) {
    asm volatile(
        "mma.sync.aligned.m16n8k16.row.col.f32.f16.f16.f32 "
        "{%0,%1,%2,%3}, {%4,%5,%6,%7}, {%8,%9}, {%0,%1,%2,%3};\n"
        : "+f"(c[0]), "+f"(c[1]), "+f"(c[2]), "+f"(c[3])
        : "r"(a[0]), "r"(a[1]), "r"(a[2]), "r"(a[3]), "r"(b[0]), "r"(b[1]));
}
__device__ __forceinline__ void red2(float* addr, float v0, float v1) {
    asm volatile("red.global.add.v2.f32 [%0], {%1, %2};"
                 :: "l"(addr), "f"(v0), "f"(v1) : "memory");
}
__device__ __forceinline__ uint32_t pack2h(float a, float b) {
    __half2 h = __floats2half2_rn(a, b);
    return *(uint32_t*)&h;
}

// ---------------- launch 0: prep (gate + x convert + out zero + scan | W convert) ----------------
__global__ void prep_kernel(const float* __restrict__ x,
                            const float* __restrict__ gw,
                            const float* __restrict__ gb,
                            const float* __restrict__ ew,
                            float* __restrict__ out) {
    int bid = blockIdx.x;

    if (bid >= NTOK) {
        // -------- convert W path --------
        size_t idx = (size_t)(bid - NTOK) * 256 + threadIdx.x;   // 8 elems per thread
        const float4* ws = (const float4*)ew;
        float4 a = ws[idx * 2], b = ws[idx * 2 + 1];
        uint4 o;
        o.x = pack2h(a.x, a.y);  o.y = pack2h(a.z, a.w);
        o.z = pack2h(b.x, b.y);  o.w = pack2h(b.z, b.w);
        ((uint4*)g_wh)[idx] = o;
        return;
    }

    // -------- gate path (single pass over x) --------
    int t = bid;
    int i = threadIdx.x;
    const float4* xs = (const float4*)(x + (size_t)t * DIN);
    float4 a = xs[i * 2], b = xs[i * 2 + 1];

    // fp16 convert (token order) + zero the out row
    {
        uint4 o;
        o.x = pack2h(a.x, a.y);  o.y = pack2h(a.z, a.w);
        o.z = pack2h(b.x, b.y);  o.w = pack2h(b.z, b.w);
        ((uint4*)(g_xh + (size_t)t * DIN))[i] = o;
        float4 z = make_float4(0.f, 0.f, 0.f, 0.f);
        float4* o4 = (float4*)(out + (size_t)t * DOUT);
        o4[i * 2]     = z;
        o4[i * 2 + 1] = z;
    }

    // gate logits from registers: this thread owns x[k], k = i*8 .. i*8+7
    float acc[NE];
#pragma unroll
    for (int e = 0; e < NE; e++) {
        const float4* gwe = (const float4*)(gw + (size_t)e * DIN + i * 8);
        float4 w0 = gwe[0], w1 = gwe[1];
        acc[e] = a.x * w0.x + a.y * w0.y + a.z * w0.z + a.w * w0.w
               + b.x * w1.x + b.y * w1.y + b.z * w1.z + b.w * w1.w;
    }
#pragma unroll
    for (int off = 16; off > 0; off >>= 1)
#pragma unroll
        for (int e = 0; e < NE; e++)
            acc[e] += __shfl_xor_sync(0xffffffffu, acc[e], off);

    __shared__ float red[NE][8];
    int warp = threadIdx.x >> 5, lane = threadIdx.x & 31;
    if (lane == 0)
#pragma unroll
        for (int e = 0; e < NE; e++) red[e][warp] = acc[e];
    __syncthreads();

    if (threadIdx.x == 0) {
        float lg[NE];
#pragma unroll
        for (int e = 0; e < NE; e++) {
            float s = 0.f;
#pragma unroll
            for (int w = 0; w < 8; w++) s += red[e][w];
            lg[e] = s + gb[e];
        }
        float m = lg[0];
#pragma unroll
        for (int e = 1; e < NE; e++) m = fmaxf(m, lg[e]);
        float pz[NE], Z = 0.f;
#pragma unroll
        for (int e = 0; e < NE; e++) { pz[e] = expf(lg[e] - m); Z += pz[e]; }
        int i1 = -1, i2 = -1; float m1 = -1.f, m2 = -1.f;
#pragma unroll
        for (int e = 0; e < NE; e++) {
            float p = pz[e];
            if (p > m1)      { m2 = m1; i2 = i1; m1 = p; i1 = e; }
            else if (p > m2) { m2 = p; i2 = e; }
        }
        float inv = 1.f / Z;
        g_topi[t * 2]     = i1;  g_topp[t * 2]     = m1 * inv;
        g_topi[t * 2 + 1] = i2;  g_topp[t * 2 + 1] = m2 * inv;
        atomicAdd(&g_cnt[i1], 1);
        atomicAdd(&g_cnt[i2], 1);

        __threadfence();
        int old = atomicAdd(&g_done, 1);
        if (old == NTOK - 1) {                 // last gate block: scan + tile table
            int off = 0, nt = 0;
            for (int e = 0; e < NE; e++) {
                g_off[e] = off;
                int c = g_cnt[e];
                g_cnt[e] = 0;                  // reset for next replay
                for (int r = 0; r < c; r += BM) {
                    g_tile_e[nt] = e;
                    g_tile_r0[nt] = off + r;
                    g_tile_rows[nt] = (c - r < BM) ? (c - r) : BM;
                    nt++;
                }
                off += c;
            }
            g_off[NE] = off;
            g_ntiles = nt;
            g_done = 0;
            __threadfence();
        }
    }
}

// ---------------- launch 1: scatter (slot assignment) ----------------
__global__ void scatter_kernel() {
    int t = blockIdx.x * blockDim.x + threadIdx.x;
    if (t >= NTOK) return;
#pragma unroll
    for (int k = 0; k < 2; k++) {
        int e = g_topi[t * 2 + k];
        float p = g_topp[t * 2 + k];
        int pos = atomicAdd(&g_pos[e], 1);
        int slot = g_off[e] + pos;
        g_tok[slot] = t;
        g_wt[slot]  = p;
    }
}

// ---------------- launch 2: reset g_pos (keeps gemm at profiled index 3) ----------------
__global__ void reset_pos_kernel() {
    if (threadIdx.x < NE) g_pos[threadIdx.x] = 0;
}

// ---------------- launch 3: grouped GEMM (R13 core, v2 vector reductions) ----------------
extern __shared__ char dsm[];

__global__ __launch_bounds__(256, 2) void gemm_kernel(const float* __restrict__ bias,
                                                      float* __restrict__ out) {
    int mt = blockIdx.y;
    if (mt >= g_ntiles) return;
    int e    = g_tile_e[mt];
    int row0 = g_tile_r0[mt];
    int rows = g_tile_rows[mt];
    int n0   = blockIdx.x * BN;

    float* wt_s = (float*)(dsm + SMEM_WT);
    int*   tok_s = (int*)(dsm + SMEM_TOK);

    int tid = threadIdx.x;
    int wid = tid >> 5, lane = tid & 31;
    if (tid < BM) {
        tok_s[tid] = (tid < rows) ? g_tok[row0 + tid] : 0;
        wt_s[tid]  = (tid < rows) ? g_wt[row0 + tid] : 0.f;
    }
    __syncthreads();

    int lrow = tid >> 1;
    int lch  = (tid & 1) * 4;
    const __half* asrc = g_xh + (size_t)tok_s[lrow] * DIN + lch * 8;
    const __half* bsrc = g_wh + ((size_t)e * DOUT + n0 + lrow) * DIN + lch * 8;

    uint32_t aS[2], bS[2];
#pragma unroll
    for (int s = 0; s < 2; s++) {
        aS[s] = (uint32_t)__cvta_generic_to_shared(dsm + s * STG_B) +
                (lrow * ASTR + lch * 8) * 2;
        bS[s] = (uint32_t)__cvta_generic_to_shared(dsm + s * STG_B + A_STG_B) +
                (lrow * ASTR + lch * 8) * 2;
    }

    auto issue = [&](int step, int buf) {
        const __half* as = asrc + step * BK;
        const __half* bs = bsrc + step * BK;
#pragma unroll
        for (int i = 0; i < 4; i++) {
            cpa16(aS[buf] + i * 16, as + i * 8);
            cpa16(bS[buf] + i * 16, bs + i * 8);
        }
    };

    int wm = wid >> 2, wn = wid & 3;
    int a_r = lane & 15, a_k = (lane >> 4) * 8;
    int b_r = ((lane >> 4) * 8) + (lane & 7), b_k = ((lane >> 3) & 1) * 8;

    uint32_t aL[2][4], bL[2][2];
#pragma unroll
    for (int s = 0; s < 2; s++) {
        char* Ab = dsm + s * STG_B;
        char* Bb = dsm + s * STG_B + A_STG_B;
#pragma unroll
        for (int im = 0; im < 4; im++)
            aL[s][im] = (uint32_t)__cvta_generic_to_shared(
                Ab + ((wm * 64 + im * 16 + a_r) * ASTR + a_k) * 2);
#pragma unroll
        for (int ip = 0; ip < 2; ip++)
            bL[s][ip] = (uint32_t)__cvta_generic_to_shared(
                Bb + ((wn * 32 + ip * 16 + b_r) * ASTR + b_k) * 2);
    }

    float acc[4][4][4];
#pragma unroll
    for (int im = 0; im < 4; im++)
#pragma unroll
        for (int in = 0; in < 4; in++)
#pragma unroll
            for (int j = 0; j < 4; j++) acc[im][in][j] = 0.f;

    issue(0, 0);
    asm volatile("cp.async.commit_group;\n");
    int cur = 0;
    for (int s = 0; s < KSTEPS; s++) {
        if (s + 1 < KSTEPS) issue(s + 1, cur ^ 1);
        asm volatile("cp.async.commit_group;\n");
        asm volatile("cp.async.wait_group 1;\n");
        __syncthreads();

#pragma unroll
        for (int kk = 0; kk < BK; kk += 16) {
            uint32_t a[4][4], b[4][2];
#pragma unroll
            for (int im = 0; im < 4; im++)
                ldsm_x4(a[im], aL[cur][im] + kk * 2);
#pragma unroll
            for (int ip = 0; ip < 2; ip++) {
                uint32_t r[4];
                ldsm_x4(r, bL[cur][ip] + kk * 2);
                b[2 * ip][0] = r[0];     b[2 * ip][1] = r[1];
                b[2 * ip + 1][0] = r[2]; b[2 * ip + 1][1] = r[3];
            }
#pragma unroll
            for (int im = 0; im < 4; im++)
#pragma unroll
                for (int in = 0; in < 4; in++)
                    mma16816(acc[im][in], a[im], b[in]);
        }
        __syncthreads();
        cur ^= 1;
    }

    // ---- epilogue: vector reductions straight into out ----
    int g = lane >> 2, tg = lane & 3;
#pragma unroll
    for (int im = 0; im < 4; im++) {
        int r0 = wm * 64 + im * 16 + g;
#pragma unroll
        for (int half = 0; half < 2; half++) {
            int r = r0 + half * 8;
            if (r < rows) {
                int t = tok_s[r];
                float w = wt_s[r];
                float* orow = out + (size_t)t * DOUT + n0;
                const float* bp = bias + (size_t)e * DOUT + n0;
#pragma unroll
                for (int in = 0; in < 4; in++) {
                    int c = wn * 32 + in * 8 + tg * 2;
                    red2(&orow[c],
                         w * (acc[im][in][2 * half]     + bp[c]),
                         w * (acc[im][in][2 * half + 1] + bp[c + 1]));
                }
            }
        }
    }
}

// ---------------- launch ----------------
extern "C" void kernel_launch(void* const* d_in, const int* in_sizes, int n_in,
                              void* d_out, int out_size) {
    const float* x  = (const float*)d_in[0];
    const float* ew = (const float*)d_in[1];
    const float* eb = (const float*)d_in[2];
    const float* gw = (const float*)d_in[3];
    const float* gb = (const float*)d_in[4];
    float* out = (float*)d_out;

    cudaFuncSetAttribute(gemm_kernel, cudaFuncAttributeMaxDynamicSharedMemorySize, SMEM_TOT);

    prep_kernel<<<NTOK + WBLKS, 256>>>(x, gw, gb, ew, out);
    scatter_kernel<<<(NTOK + 255) / 256, 256>>>();
    reset_pos_kernel<<<1, 32>>>();
    gemm_kernel<<<dim3(NTILE, MAXT), 256, SMEM_TOT>>>(eb, out);   // profiled slot
}